// round 10
// baseline (speedup 1.0000x reference)
#include <cuda_runtime.h>
#include <cuda_fp16.h>
#include <cstdint>

#define BB 16
#define LL 4096
#define DD 512
#define KK 2048
#define NROWS 32768

#define MT 128            // rows per CTA
#define NT 128            // codes per CTA
#define KC 64             // k elems per stage (hi-only -> 128B rows)
#define NSTAGE (DD / KC)  // 8
#define NCTQ (KK / NT)    // 16
#define CBSCALE 2048.0f   // codebook scale: argmin-invariant, keeps fp16 in range

// ------------------------------------------------------------- device scratch
__device__ float   g_means[NROWS * DD];   // fp32 (exact rescore)
__device__ __half  g_mh[NROWS * DD];      // means (fp16)
__device__ __half  g_ch[KK * DD];         // codebook*2048 (fp16)
__device__ int     g_idx[NROWS];
__device__ float   g_cbsq[KK];
__device__ float   g_s[KK];
__device__ float4  g_part[NROWS * NCTQ];  // per (row, ctile): v1,i1,v2,i2

// ------------------------------------------------------------- PTX helpers
__device__ __forceinline__ uint32_t smem_u32(const void* p) {
    uint32_t a;
    asm("{ .reg .u64 t; cvta.to.shared.u64 t, %1; cvt.u32.u64 %0, t; }" : "=r"(a) : "l"(p));
    return a;
}
#define CP16(dst, src) \
    asm volatile("cp.async.cg.shared.global [%0], [%1], 16;" :: "r"(dst), "l"(src))
#define CP_COMMIT() asm volatile("cp.async.commit_group;" ::: "memory")
#define CP_WAIT1()  asm volatile("cp.async.wait_group 1;" ::: "memory")
#define LDSM_X4(r0, r1, r2, r3, addr)                                             \
    asm volatile("ldmatrix.sync.aligned.m8n8.x4.shared.b16 {%0,%1,%2,%3}, [%4];"  \
        : "=r"(r0), "=r"(r1), "=r"(r2), "=r"(r3) : "r"(addr))
__device__ __forceinline__ void mma_f16(float* d, const uint32_t* a, const uint32_t* b) {
    asm volatile(
        "mma.sync.aligned.m16n8k16.row.col.f32.f16.f16.f32 "
        "{%0,%1,%2,%3}, {%4,%5,%6,%7}, {%8,%9}, {%0,%1,%2,%3};"
        : "+f"(d[0]), "+f"(d[1]), "+f"(d[2]), "+f"(d[3])
        : "r"(a[0]), "r"(a[1]), "r"(a[2]), "r"(a[3]), "r"(b[0]), "r"(b[1]));
}
__device__ __forceinline__ uint32_t pack_h2(__half a, __half b) {
    return (uint32_t)__half_as_ushort(a) | ((uint32_t)__half_as_ushort(b) << 16);
}

// ------------------------------------------------------------- K1: means + fp16
__global__ void means_kernel(const float4* __restrict__ E) {
    int i = blockIdx.x * blockDim.x + threadIdx.x;
    const int D4 = DD / 4;
    if (i >= NROWS * D4) return;
    int row = i / D4, d4 = i - row * D4;
    float4 a = E[(2 * row) * D4 + d4];
    float4 b = E[(2 * row + 1) * D4 + d4];
    float4 m;
    m.x = 0.5f * (a.x + b.x); m.y = 0.5f * (a.y + b.y);
    m.z = 0.5f * (a.z + b.z); m.w = 0.5f * (a.w + b.w);
    ((float4*)g_means)[i] = m;
    ((uint2*)g_mh)[i] = make_uint2(
        pack_h2(__float2half_rn(m.x), __float2half_rn(m.y)),
        pack_h2(__float2half_rn(m.z), __float2half_rn(m.w)));
}

// ------------------------------------------------------------- K1b: codebook scale -> fp16
__global__ void cbsplit_kernel(const float4* __restrict__ Cb4) {
    int i = blockIdx.x * blockDim.x + threadIdx.x;
    if (i >= KK * DD / 4) return;
    float4 m = Cb4[i];
    ((uint2*)g_ch)[i] = make_uint2(
        pack_h2(__float2half_rn(m.x * CBSCALE), __float2half_rn(m.y * CBSCALE)),
        pack_h2(__float2half_rn(m.z * CBSCALE), __float2half_rn(m.w * CBSCALE)));
}

// ------------------------------------------------------------- K2: prep (cbsq + per-code loss)
__global__ __launch_bounds__(256) void prep_kernel(const float* __restrict__ Cb,
                                                   const float* __restrict__ W,
                                                   const float* __restrict__ bias) {
    __shared__ float Ck[8][DD];
    __shared__ float sred[8][8];
    int tid = threadIdx.x, warp = tid >> 5, lane = tid & 31;
    int k0 = blockIdx.x * 8;
    for (int i = tid; i < 8 * DD; i += 256) {
        int kk = i / DD, d = i - kk * DD;
        Ck[kk][d] = Cb[(k0 + kk) * DD + d];
    }
    __syncthreads();
    {
        float sq = 0.f;
        for (int d = lane; d < DD; d += 32) { float v = Ck[warp][d]; sq = fmaf(v, v, sq); }
        #pragma unroll
        for (int o = 16; o; o >>= 1) sq += __shfl_xor_sync(0xffffffffu, sq, o);
        if (lane == 0) g_cbsq[k0 + warp] = sq;
    }
    float sacc[8];
    #pragma unroll
    for (int kk = 0; kk < 8; kk++) sacc[kk] = 0.f;
    for (int e = warp; e < DD; e += 8) {
        float p[8];
        #pragma unroll
        for (int kk = 0; kk < 8; kk++) p[kk] = 0.f;
        for (int d = lane; d < DD; d += 32) {
            float wv = W[e * DD + d];
            #pragma unroll
            for (int kk = 0; kk < 8; kk++) p[kk] = fmaf(Ck[kk][d], wv, p[kk]);
        }
        #pragma unroll
        for (int kk = 0; kk < 8; kk++) {
            #pragma unroll
            for (int o = 16; o; o >>= 1) p[kk] += __shfl_xor_sync(0xffffffffu, p[kk], o);
        }
        if (lane == 0) {
            float be = bias[e];
            #pragma unroll
            for (int kk = 0; kk < 8; kk++) {
                float diff = p[kk] + be - Ck[kk][e];
                sacc[kk] = fmaf(diff, diff, sacc[kk]);
            }
        }
    }
    if (lane == 0) {
        #pragma unroll
        for (int kk = 0; kk < 8; kk++) sred[warp][kk] = sacc[kk];
    }
    __syncthreads();
    if (tid < 8) {
        float s = 0.f;
        #pragma unroll
        for (int w = 0; w < 8; w++) s += sred[w][tid];
        g_s[k0 + tid] = s;
    }
}

// ------------------------------------------------------------- K3: single-pass fp16 GEMM + top-2
// 512 threads, 16 warps (4x4), warp tile 32x32. Double-buffered cp.async.
// Rows (A and B): 128B = 64 fp16 of one k-stage, 16B chunks XOR-swizzled by row&7.
#define SMEM_GEMM 66048

__global__ __launch_bounds__(512, 1) void gemm_argmin() {
    extern __shared__ char smraw[];
    uint32_t sb = smem_u32(smraw);
    int tid = threadIdx.x;
    int lane = tid & 31, wid = tid >> 5;
    int wm = wid >> 2, wn = wid & 3;        // warp tile: rows wm*32, cols wn*32
    int row0 = blockIdx.x * MT;
    int ctbase = blockIdx.y * NT;

    const uint32_t smA[2] = { sb, sb + 16384 };
    const uint32_t smB[2] = { sb + 32768, sb + 49152 };
    float* cbs = (float*)(smraw + 65536);
    float4* red = (float4*)smraw;           // alias: used only after mainloop

    if (tid < NT) cbs[tid] = g_cbsq[ctbase + tid] * CBSCALE;

    // ldmatrix lane-invariants
    const int rA = lane & 15, cA = lane >> 4;        // A: rows 0-15, 16B half of k16
    const int rB = (lane & 7) | ((lane >> 4) << 3);  // B: n row within 16
    const int cB = (lane >> 3) & 1;                  // B: 16B half of k16

    float acc[2][4][4];
    #pragma unroll
    for (int a = 0; a < 2; a++)
        #pragma unroll
        for (int b = 0; b < 4; b++)
            #pragma unroll
            for (int c = 0; c < 4; c++) acc[a][b][c] = 0.f;

    const int ldrow = tid >> 2, ldc = tid & 3;   // load slot: row 0-127, 32B pair 0-3

    auto issue = [&](int s, int b) {
        uint32_t x = ldrow & 7;
        uint32_t ch0 = 2 * ldc, ch1 = 2 * ldc + 1;
        {
            const __half* p = g_mh + (size_t)(row0 + ldrow) * DD + s * KC + ldc * 16;
            uint32_t base = smA[b] + ldrow * 128;
            CP16(base + ((ch0 ^ x) << 4), p);
            CP16(base + ((ch1 ^ x) << 4), p + 8);
        }
        {
            const __half* p = g_ch + (size_t)(ctbase + ldrow) * DD + s * KC + ldc * 16;
            uint32_t base = smB[b] + ldrow * 128;
            CP16(base + ((ch0 ^ x) << 4), p);
            CP16(base + ((ch1 ^ x) << 4), p + 8);
        }
    };

    issue(0, 0); CP_COMMIT();
    issue(1, 1); CP_COMMIT();

    for (int s = 0; s < NSTAGE; s++) {
        const int b = s & 1;
        CP_WAIT1();
        __syncthreads();

        #pragma unroll
        for (int kk = 0; kk < 4; kk++) {
            uint32_t ah[2][4], bh[4][2];
            #pragma unroll
            for (int mf = 0; mf < 2; mf++) {
                int row = wm * 32 + mf * 16 + rA;
                uint32_t ba = smA[b] + row * 128;
                uint32_t x = (uint32_t)(row & 7);
                LDSM_X4(ah[mf][0], ah[mf][1], ah[mf][2], ah[mf][3],
                        ba + ((((uint32_t)(2 * kk + cA)) ^ x) << 4));
            }
            #pragma unroll
            for (int np = 0; np < 2; np++) {
                int n = wn * 32 + np * 16 + rB;
                uint32_t bb = smB[b] + n * 128;
                uint32_t x = (uint32_t)(n & 7);
                uint32_t t0, t1, t2, t3;
                LDSM_X4(t0, t1, t2, t3, bb + ((((uint32_t)(2 * kk + cB)) ^ x) << 4));
                bh[2 * np][0] = t0; bh[2 * np][1] = t1;
                bh[2 * np + 1][0] = t2; bh[2 * np + 1][1] = t3;
            }
            #pragma unroll
            for (int mf = 0; mf < 2; mf++)
                #pragma unroll
                for (int nf = 0; nf < 4; nf++)
                    mma_f16(acc[mf][nf], ah[mf], bh[nf]);
        }
        __syncthreads();
        if (s + 2 < NSTAGE) issue(s + 2, b);
        CP_COMMIT();
    }
    __syncthreads();   // before aliasing smA as red[]

    // ---- epilogue: scores + per-row top-2 ----
    int g = lane >> 2, q = lane & 3;
    #pragma unroll
    for (int mf = 0; mf < 2; mf++) {
        #pragma unroll
        for (int half = 0; half < 2; half++) {
            int rloc = wm * 32 + mf * 16 + half * 8 + g;
            float v1 = 3.4e38f, v2 = 3.4e38f;
            int i1 = 0, i2 = 0;
            #pragma unroll
            for (int nf = 0; nf < 4; nf++) {
                #pragma unroll
                for (int j = 0; j < 2; j++) {
                    int cloc = wn * 32 + nf * 8 + 2 * q + j;
                    float sc = fmaf(-2.0f, acc[mf][nf][half * 2 + j], cbs[cloc]);
                    int code = ctbase + cloc;
                    if (sc < v1) { v2 = v1; i2 = i1; v1 = sc; i1 = code; }
                    else if (sc < v2) { v2 = sc; i2 = code; }
                }
            }
            #pragma unroll
            for (int o = 1; o <= 2; o <<= 1) {
                float w1 = __shfl_xor_sync(0xffffffffu, v1, o);
                int   j1 = __shfl_xor_sync(0xffffffffu, i1, o);
                float w2 = __shfl_xor_sync(0xffffffffu, v2, o);
                int   j2 = __shfl_xor_sync(0xffffffffu, i2, o);
                if (w1 < v1 || (w1 == v1 && j1 < i1)) { v2 = v1; i2 = i1; v1 = w1; i1 = j1; }
                else if (w1 < v2 || (w1 == v2 && j1 < i2)) { v2 = w1; i2 = j1; }
                if (w2 < v1 || (w2 == v1 && j2 < i1)) { v2 = v1; i2 = i1; v1 = w2; i1 = j2; }
                else if (w2 < v2 || (w2 == v2 && j2 < i2)) { v2 = w2; i2 = j2; }
            }
            if (q == 0)
                red[rloc * 4 + wn] =
                    make_float4(v1, __int_as_float(i1), v2, __int_as_float(i2));
        }
    }
    __syncthreads();
    if (tid < MT) {
        float v1 = 3.4e38f, v2 = 3.4e38f;
        int i1 = 0x7fffffff, i2 = 0x7fffffff;
        #pragma unroll
        for (int w = 0; w < 4; w++) {
            float4 p = red[tid * 4 + w];
            float w1 = p.x, w2 = p.z;
            int j1 = __float_as_int(p.y), j2 = __float_as_int(p.w);
            if (w1 < v1 || (w1 == v1 && j1 < i1)) { v2 = v1; i2 = i1; v1 = w1; i1 = j1; }
            else if (w1 < v2 || (w1 == v2 && j1 < i2)) { v2 = w1; i2 = j1; }
            if (w2 < v1 || (w2 == v1 && j2 < i1)) { v2 = v1; i2 = i1; v1 = w2; i1 = j2; }
            else if (w2 < v2 || (w2 == v2 && j2 < i2)) { v2 = w2; i2 = j2; }
        }
        g_part[(size_t)(row0 + tid) * NCTQ + blockIdx.y] =
            make_float4(v1, __int_as_float(i1), v2, __int_as_float(i2));
    }
}

// ------------------------------------------------------------- K4: exact rescore of all 32
// candidates (top-2 from each of 16 tiles) + argmin + gather.  Warp per row.
__global__ __launch_bounds__(256) void combine_kernel(const float* __restrict__ Cb,
                                                      float* __restrict__ out_idx_f,
                                                      float4* __restrict__ out_emb4) {
    int row = blockIdx.x * 8 + (threadIdx.x >> 5);
    int lane = threadIdx.x & 31;

    float4 p = g_part[(size_t)row * NCTQ + (lane & 15)];
    int cand = (lane < 16) ? __float_as_int(p.y) : __float_as_int(p.w);

    // exact fp32 score for this candidate
    const float4* m4 = (const float4*)&g_means[(size_t)row * DD];
    const float4* c4 = (const float4*)&Cb[(size_t)cand * DD];
    float a0 = 0.f, a1 = 0.f, a2 = 0.f, a3 = 0.f;
    #pragma unroll 8
    for (int d = 0; d < DD / 4; d++) {
        float4 mv = m4[d];
        float4 cv = c4[d];
        a0 = fmaf(mv.x, cv.x, a0);
        a1 = fmaf(mv.y, cv.y, a1);
        a2 = fmaf(mv.z, cv.z, a2);
        a3 = fmaf(mv.w, cv.w, a3);
    }
    float dot = (a0 + a1) + (a2 + a3);
    float sv = fmaf(-2.f, dot, g_cbsq[cand]);

    // warp all-reduce argmin with lowest-index tiebreak
    float bv = sv;
    int bi = cand;
    #pragma unroll
    for (int o = 16; o; o >>= 1) {
        float wv = __shfl_xor_sync(0xffffffffu, bv, o);
        int   wi = __shfl_xor_sync(0xffffffffu, bi, o);
        if (wv < bv || (wv == bv && wi < bi)) { bv = wv; bi = wi; }
    }
    if (lane == 0) {
        g_idx[row] = bi;
        out_idx_f[row] = (float)bi;
    }
    // fused gather: write winner's embedding (codebook L2-hot)
    const float4* src = (const float4*)&Cb[(size_t)bi * DD];
    float4* dst = out_emb4 + (size_t)row * (DD / 4);
    #pragma unroll
    for (int j = 0; j < 4; j++)
        dst[lane + 32 * j] = src[lane + 32 * j];
}

// ------------------------------------------------------------- K5: loss
__global__ void loss_kernel(float* __restrict__ out_loss) {
    __shared__ float red[1024];
    float s = 0.f;
    for (int n = threadIdx.x; n < NROWS; n += 1024) s += g_s[g_idx[n]];
    red[threadIdx.x] = s;
    __syncthreads();
    for (int st = 512; st > 0; st >>= 1) {
        if (threadIdx.x < st) red[threadIdx.x] += red[threadIdx.x + st];
        __syncthreads();
    }
    if (threadIdx.x == 0)
        out_loss[0] = red[0] / (float)((long long)NROWS * DD);
}

// -------------------------------------------------------------
extern "C" void kernel_launch(void* const* d_in, const int* in_sizes, int n_in,
                              void* d_out, int out_size) {
    const float* E    = (const float*)d_in[1];
    const float* Cb   = (const float*)d_in[2];
    const float* W    = (const float*)d_in[3];
    const float* bias = (const float*)d_in[4];

    float* out      = (float*)d_out;
    float* out_idx  = out;
    float* out_emb  = out + NROWS;
    float* out_loss = out + NROWS + NROWS * DD;

    cudaFuncSetAttribute(gemm_argmin, cudaFuncAttributeMaxDynamicSharedMemorySize, SMEM_GEMM);

    means_kernel<<<(NROWS * (DD / 4) + 255) / 256, 256>>>((const float4*)E);
    cbsplit_kernel<<<(KK * DD / 4 + 255) / 256, 256>>>((const float4*)Cb);
    prep_kernel<<<KK / 8, 256>>>(Cb, W, bias);
    gemm_argmin<<<dim3(NROWS / MT, NCTQ), 512, SMEM_GEMM>>>();
    combine_kernel<<<NROWS / 8, 256>>>(Cb, out_idx, (float4*)out_emb);
    loss_kernel<<<1, 1024>>>(out_loss);
}

// round 11
// speedup vs baseline: 2.0798x; 2.0798x over previous
#include <cuda_runtime.h>
#include <cuda_fp16.h>
#include <cstdint>

#define BB 16
#define LL 4096
#define DD 512
#define KK 2048
#define NROWS 32768

#define MT 256            // rows per CTA
#define NT 128            // codes per CTA
#define KC 64             // k elems per stage (128B rows)
#define NSTAGE (DD / KC)  // 8
#define NCTQ (KK / NT)    // 16
#define CBSCALE 2048.0f   // codebook scale: argmin-invariant, keeps fp16 in range
#define MARGIN 2.0f       // rescore margin (scaled units), >> worst-case fp16 score err

// ------------------------------------------------------------- device scratch
__device__ float   g_means[NROWS * DD];   // fp32 (exact rescore)
__device__ __half  g_mh[NROWS * DD];      // means (fp16)
__device__ __half  g_ch[KK * DD];         // codebook*2048 (fp16)
__device__ int     g_idx[NROWS];
__device__ float   g_cbsq[KK];
__device__ float   g_s[KK];
__device__ float4  g_part[NROWS * NCTQ];  // per (row, ctile): v1,i1,v2,i2

// ------------------------------------------------------------- PTX helpers
__device__ __forceinline__ uint32_t smem_u32(const void* p) {
    uint32_t a;
    asm("{ .reg .u64 t; cvta.to.shared.u64 t, %1; cvt.u32.u64 %0, t; }" : "=r"(a) : "l"(p));
    return a;
}
#define CP16(dst, src) \
    asm volatile("cp.async.cg.shared.global [%0], [%1], 16;" :: "r"(dst), "l"(src))
#define CP_COMMIT() asm volatile("cp.async.commit_group;" ::: "memory")
#define CP_WAIT1()  asm volatile("cp.async.wait_group 1;" ::: "memory")
#define LDSM_X4(r0, r1, r2, r3, addr)                                             \
    asm volatile("ldmatrix.sync.aligned.m8n8.x4.shared.b16 {%0,%1,%2,%3}, [%4];"  \
        : "=r"(r0), "=r"(r1), "=r"(r2), "=r"(r3) : "r"(addr))
__device__ __forceinline__ void mma_f16(float* d, const uint32_t* a, const uint32_t* b) {
    asm volatile(
        "mma.sync.aligned.m16n8k16.row.col.f32.f16.f16.f32 "
        "{%0,%1,%2,%3}, {%4,%5,%6,%7}, {%8,%9}, {%0,%1,%2,%3};"
        : "+f"(d[0]), "+f"(d[1]), "+f"(d[2]), "+f"(d[3])
        : "r"(a[0]), "r"(a[1]), "r"(a[2]), "r"(a[3]), "r"(b[0]), "r"(b[1]));
}
__device__ __forceinline__ uint32_t pack_h2(__half a, __half b) {
    return (uint32_t)__half_as_ushort(a) | ((uint32_t)__half_as_ushort(b) << 16);
}

// ------------------------------------------------------------- K1: means + fp16
__global__ void means_kernel(const float4* __restrict__ E) {
    int i = blockIdx.x * blockDim.x + threadIdx.x;
    const int D4 = DD / 4;
    if (i >= NROWS * D4) return;
    int row = i / D4, d4 = i - row * D4;
    float4 a = E[(2 * row) * D4 + d4];
    float4 b = E[(2 * row + 1) * D4 + d4];
    float4 m;
    m.x = 0.5f * (a.x + b.x); m.y = 0.5f * (a.y + b.y);
    m.z = 0.5f * (a.z + b.z); m.w = 0.5f * (a.w + b.w);
    ((float4*)g_means)[i] = m;
    ((uint2*)g_mh)[i] = make_uint2(
        pack_h2(__float2half_rn(m.x), __float2half_rn(m.y)),
        pack_h2(__float2half_rn(m.z), __float2half_rn(m.w)));
}

// ------------------------------------------------------------- K1b: codebook scale -> fp16
__global__ void cbsplit_kernel(const float4* __restrict__ Cb4) {
    int i = blockIdx.x * blockDim.x + threadIdx.x;
    if (i >= KK * DD / 4) return;
    float4 m = Cb4[i];
    ((uint2*)g_ch)[i] = make_uint2(
        pack_h2(__float2half_rn(m.x * CBSCALE), __float2half_rn(m.y * CBSCALE)),
        pack_h2(__float2half_rn(m.z * CBSCALE), __float2half_rn(m.w * CBSCALE)));
}

// ------------------------------------------------------------- K2: prep (cbsq + per-code loss)
__global__ __launch_bounds__(256) void prep_kernel(const float* __restrict__ Cb,
                                                   const float* __restrict__ W,
                                                   const float* __restrict__ bias) {
    __shared__ float Ck[8][DD];
    __shared__ float sred[8][8];
    int tid = threadIdx.x, warp = tid >> 5, lane = tid & 31;
    int k0 = blockIdx.x * 8;
    for (int i = tid; i < 8 * DD; i += 256) {
        int kk = i / DD, d = i - kk * DD;
        Ck[kk][d] = Cb[(k0 + kk) * DD + d];
    }
    __syncthreads();
    {
        float sq = 0.f;
        for (int d = lane; d < DD; d += 32) { float v = Ck[warp][d]; sq = fmaf(v, v, sq); }
        #pragma unroll
        for (int o = 16; o; o >>= 1) sq += __shfl_xor_sync(0xffffffffu, sq, o);
        if (lane == 0) g_cbsq[k0 + warp] = sq;
    }
    float sacc[8];
    #pragma unroll
    for (int kk = 0; kk < 8; kk++) sacc[kk] = 0.f;
    for (int e = warp; e < DD; e += 8) {
        float p[8];
        #pragma unroll
        for (int kk = 0; kk < 8; kk++) p[kk] = 0.f;
        for (int d = lane; d < DD; d += 32) {
            float wv = W[e * DD + d];
            #pragma unroll
            for (int kk = 0; kk < 8; kk++) p[kk] = fmaf(Ck[kk][d], wv, p[kk]);
        }
        #pragma unroll
        for (int kk = 0; kk < 8; kk++) {
            #pragma unroll
            for (int o = 16; o; o >>= 1) p[kk] += __shfl_xor_sync(0xffffffffu, p[kk], o);
        }
        if (lane == 0) {
            float be = bias[e];
            #pragma unroll
            for (int kk = 0; kk < 8; kk++) {
                float diff = p[kk] + be - Ck[kk][e];
                sacc[kk] = fmaf(diff, diff, sacc[kk]);
            }
        }
    }
    if (lane == 0) {
        #pragma unroll
        for (int kk = 0; kk < 8; kk++) sred[warp][kk] = sacc[kk];
    }
    __syncthreads();
    if (tid < 8) {
        float s = 0.f;
        #pragma unroll
        for (int w = 0; w < 8; w++) s += sred[w][tid];
        g_s[k0 + tid] = s;
    }
}

// ------------------------------------------------------------- K3: single-pass fp16 GEMM + top-2
// CTA tile 256x128, 512 threads, 16 warps (4 row x 4 col), warp tile 64x32.
// Double-buffered cp.async. Rows: 128B = 64 fp16 of one k-stage, 16B chunks
// XOR-swizzled by row&7.
// smem: A0[0,32K) A1[32K,64K) B0[64K,80K) B1[80K,96K) cbs@98304. red aliases A0.
#define SMEM_GEMM 98816

__global__ __launch_bounds__(512, 1) void gemm_argmin() {
    extern __shared__ char smraw[];
    uint32_t sb = smem_u32(smraw);
    int tid = threadIdx.x;
    int lane = tid & 31, wid = tid >> 5;
    int wm = wid >> 2, wn = wid & 3;        // warp tile: rows wm*64, cols wn*32
    int row0 = blockIdx.x * MT;
    int ctbase = blockIdx.y * NT;

    const uint32_t smA[2] = { sb, sb + 32768 };
    const uint32_t smB[2] = { sb + 65536, sb + 81920 };
    float* cbs = (float*)(smraw + 98304);
    float4* red = (float4*)smraw;           // alias: used only after mainloop (16KB < 32KB)

    if (tid < NT) cbs[tid] = g_cbsq[ctbase + tid] * CBSCALE;

    // ldmatrix lane-invariants
    const int rA = lane & 15, cA = lane >> 4;        // A: rows 0-15, 16B half of k16
    const int rB = (lane & 7) | ((lane >> 4) << 3);  // B: n row within 16
    const int cB = (lane >> 3) & 1;                  // B: 16B half of k16

    float acc[4][4][4];
    #pragma unroll
    for (int a = 0; a < 4; a++)
        #pragma unroll
        for (int b = 0; b < 4; b++)
            #pragma unroll
            for (int c = 0; c < 4; c++) acc[a][b][c] = 0.f;

    // loaders: A row tid>>1 (0..255), chunk group (tid&1)*4; B row tid>>2, pair (tid&3)*2
    const int arow = tid >> 1, ah4 = (tid & 1) * 4;
    const int brow = tid >> 2, bc2 = (tid & 3) * 2;

    auto issue = [&](int s, int b) {
        {
            uint32_t x = (uint32_t)(arow & 7);
            const __half* p = g_mh + (size_t)(row0 + arow) * DD + s * KC + ah4 * 8;
            uint32_t base = smA[b] + arow * 128;
            #pragma unroll
            for (int c = 0; c < 4; c++)
                CP16(base + ((((uint32_t)(ah4 + c)) ^ x) << 4), p + 8 * c);
        }
        {
            uint32_t x = (uint32_t)(brow & 7);
            const __half* p = g_ch + (size_t)(ctbase + brow) * DD + s * KC + bc2 * 8;
            uint32_t base = smB[b] + brow * 128;
            CP16(base + ((((uint32_t)bc2) ^ x) << 4), p);
            CP16(base + ((((uint32_t)(bc2 + 1)) ^ x) << 4), p + 8);
        }
    };

    issue(0, 0); CP_COMMIT();
    issue(1, 1); CP_COMMIT();

    for (int s = 0; s < NSTAGE; s++) {
        const int b = s & 1;
        CP_WAIT1();
        __syncthreads();

        #pragma unroll
        for (int kk = 0; kk < 4; kk++) {
            uint32_t ah[4][4], bh[4][2];
            #pragma unroll
            for (int mf = 0; mf < 4; mf++) {
                int row = wm * 64 + mf * 16 + rA;
                uint32_t ba = smA[b] + row * 128;
                uint32_t x = (uint32_t)(row & 7);
                LDSM_X4(ah[mf][0], ah[mf][1], ah[mf][2], ah[mf][3],
                        ba + ((((uint32_t)(2 * kk + cA)) ^ x) << 4));
            }
            #pragma unroll
            for (int np = 0; np < 2; np++) {
                int n = wn * 32 + np * 16 + rB;
                uint32_t bb = smB[b] + n * 128;
                uint32_t x = (uint32_t)(n & 7);
                uint32_t t0, t1, t2, t3;
                LDSM_X4(t0, t1, t2, t3, bb + ((((uint32_t)(2 * kk + cB)) ^ x) << 4));
                bh[2 * np][0] = t0; bh[2 * np][1] = t1;
                bh[2 * np + 1][0] = t2; bh[2 * np + 1][1] = t3;
            }
            #pragma unroll
            for (int mf = 0; mf < 4; mf++)
                #pragma unroll
                for (int nf = 0; nf < 4; nf++)
                    mma_f16(acc[mf][nf], ah[mf], bh[nf]);
        }
        __syncthreads();
        if (s + 2 < NSTAGE) issue(s + 2, b);
        CP_COMMIT();
    }
    __syncthreads();   // before aliasing smA as red[]

    // ---- epilogue: scores + per-row top-2 ----
    int g = lane >> 2, q = lane & 3;
    #pragma unroll
    for (int mf = 0; mf < 4; mf++) {
        #pragma unroll
        for (int half = 0; half < 2; half++) {
            int rloc = wm * 64 + mf * 16 + half * 8 + g;
            float v1 = 3.4e38f, v2 = 3.4e38f;
            int i1 = 0, i2 = 0;
            #pragma unroll
            for (int nf = 0; nf < 4; nf++) {
                #pragma unroll
                for (int j = 0; j < 2; j++) {
                    int cloc = wn * 32 + nf * 8 + 2 * q + j;
                    float sc = fmaf(-2.0f, acc[mf][nf][half * 2 + j], cbs[cloc]);
                    int code = ctbase + cloc;
                    if (sc < v1) { v2 = v1; i2 = i1; v1 = sc; i1 = code; }
                    else if (sc < v2) { v2 = sc; i2 = code; }
                }
            }
            #pragma unroll
            for (int o = 1; o <= 2; o <<= 1) {
                float w1 = __shfl_xor_sync(0xffffffffu, v1, o);
                int   j1 = __shfl_xor_sync(0xffffffffu, i1, o);
                float w2 = __shfl_xor_sync(0xffffffffu, v2, o);
                int   j2 = __shfl_xor_sync(0xffffffffu, i2, o);
                if (w1 < v1 || (w1 == v1 && j1 < i1)) { v2 = v1; i2 = i1; v1 = w1; i1 = j1; }
                else if (w1 < v2 || (w1 == v2 && j1 < i2)) { v2 = w1; i2 = j1; }
                if (w2 < v1 || (w2 == v1 && j2 < i1)) { v2 = v1; i2 = i1; v1 = w2; i1 = j2; }
                else if (w2 < v2 || (w2 == v2 && j2 < i2)) { v2 = w2; i2 = j2; }
            }
            if (q == 0)
                red[rloc * 4 + wn] =
                    make_float4(v1, __int_as_float(i1), v2, __int_as_float(i2));
        }
    }
    __syncthreads();
    if (tid < MT) {
        float v1 = 3.4e38f, v2 = 3.4e38f;
        int i1 = 0x7fffffff, i2 = 0x7fffffff;
        #pragma unroll
        for (int w = 0; w < 4; w++) {
            float4 p = red[tid * 4 + w];
            float w1 = p.x, w2 = p.z;
            int j1 = __float_as_int(p.y), j2 = __float_as_int(p.w);
            if (w1 < v1 || (w1 == v1 && j1 < i1)) { v2 = v1; i2 = i1; v1 = w1; i1 = j1; }
            else if (w1 < v2 || (w1 == v2 && j1 < i2)) { v2 = w1; i2 = j1; }
            if (w2 < v1 || (w2 == v1 && j2 < i1)) { v2 = v1; i2 = i1; v1 = w2; i1 = j2; }
            else if (w2 < v2 || (w2 == v2 && j2 < i2)) { v2 = w2; i2 = j2; }
        }
        g_part[(size_t)(row0 + tid) * NCTQ + blockIdx.y] =
            make_float4(v1, __int_as_float(i1), v2, __int_as_float(i2));
    }
}

// ------------------------------------------------------------- K4: margin-pruned exact rescore
// Warp per row: 32 candidates (top-2 x 16 tiles); exact-rescore only those within
// MARGIN of the fp16 min, warp-cooperatively (coalesced). Then argmin + gather.
__global__ __launch_bounds__(256) void combine_kernel(const float* __restrict__ Cb,
                                                      float* __restrict__ out_idx_f,
                                                      float4* __restrict__ out_emb4) {
    int row = blockIdx.x * 8 + (threadIdx.x >> 5);
    int lane = threadIdx.x & 31;

    float4 p = g_part[(size_t)row * NCTQ + (lane & 15)];
    float v  = (lane < 16) ? p.x : p.z;
    int   ci = (lane < 16) ? __float_as_int(p.y) : __float_as_int(p.w);

    float vmin = v;
    #pragma unroll
    for (int o = 16; o; o >>= 1) vmin = fminf(vmin, __shfl_xor_sync(0xffffffffu, vmin, o));

    unsigned mask = __ballot_sync(0xffffffffu, v <= vmin + MARGIN);

    const float4* m4 = (const float4*)&g_means[(size_t)row * DD];
    float bv = 3.4e38f;
    int bi = 0x7fffffff;
    while (mask) {
        int src = __ffs(mask) - 1;
        mask &= mask - 1;
        int cand = __shfl_sync(0xffffffffu, ci, src);
        const float4* c4 = (const float4*)&Cb[(size_t)cand * DD];
        float a0 = 0.f, a1 = 0.f, a2 = 0.f, a3 = 0.f;
        #pragma unroll
        for (int j = 0; j < 4; j++) {
            float4 mv = m4[lane + 32 * j];
            float4 cv = c4[lane + 32 * j];
            a0 = fmaf(mv.x, cv.x, a0);
            a1 = fmaf(mv.y, cv.y, a1);
            a2 = fmaf(mv.z, cv.z, a2);
            a3 = fmaf(mv.w, cv.w, a3);
        }
        float dot = (a0 + a1) + (a2 + a3);
        #pragma unroll
        for (int o = 16; o; o >>= 1) dot += __shfl_xor_sync(0xffffffffu, dot, o);
        float sv = fmaf(-2.f, dot, g_cbsq[cand]);
        if (sv < bv || (sv == bv && cand < bi)) { bv = sv; bi = cand; }
    }
    if (lane == 0) {
        g_idx[row] = bi;
        out_idx_f[row] = (float)bi;
    }
    // fused gather (coalesced, codebook L2-hot)
    const float4* src4 = (const float4*)&Cb[(size_t)bi * DD];
    float4* dst = out_emb4 + (size_t)row * (DD / 4);
    #pragma unroll
    for (int j = 0; j < 4; j++)
        dst[lane + 32 * j] = src4[lane + 32 * j];
}

// ------------------------------------------------------------- K5: loss
__global__ void loss_kernel(float* __restrict__ out_loss) {
    __shared__ float red[1024];
    float s = 0.f;
    for (int n = threadIdx.x; n < NROWS; n += 1024) s += g_s[g_idx[n]];
    red[threadIdx.x] = s;
    __syncthreads();
    for (int st = 512; st > 0; st >>= 1) {
        if (threadIdx.x < st) red[threadIdx.x] += red[threadIdx.x + st];
        __syncthreads();
    }
    if (threadIdx.x == 0)
        out_loss[0] = red[0] / (float)((long long)NROWS * DD);
}

// -------------------------------------------------------------
extern "C" void kernel_launch(void* const* d_in, const int* in_sizes, int n_in,
                              void* d_out, int out_size) {
    const float* E    = (const float*)d_in[1];
    const float* Cb   = (const float*)d_in[2];
    const float* W    = (const float*)d_in[3];
    const float* bias = (const float*)d_in[4];

    float* out      = (float*)d_out;
    float* out_idx  = out;
    float* out_emb  = out + NROWS;
    float* out_loss = out + NROWS + NROWS * DD;

    cudaFuncSetAttribute(gemm_argmin, cudaFuncAttributeMaxDynamicSharedMemorySize, SMEM_GEMM);

    means_kernel<<<(NROWS * (DD / 4) + 255) / 256, 256>>>((const float4*)E);
    cbsplit_kernel<<<(KK * DD / 4 + 255) / 256, 256>>>((const float4*)Cb);
    prep_kernel<<<KK / 8, 256>>>(Cb, W, bias);
    gemm_argmin<<<dim3(NROWS / MT, NCTQ), 512, SMEM_GEMM>>>();
    combine_kernel<<<NROWS / 8, 256>>>(Cb, out_idx, (float4*)out_emb);
    loss_kernel<<<1, 1024>>>(out_loss);
}